// round 2
// baseline (speedup 1.0000x reference)
#include <cuda_runtime.h>
#include <math.h>

// Problem constants: x[2,32,8192,128] f32, codebook[4] f32, projection[128,128] f32
#define DIMV 128
#define NTOK (2*32*8192)                  // 524288 tokens
#define NELEM_LL (524288LL * 128LL)       // 67108864
#define WARPS_PER_BLOCK 16
#define TOK_PER_WARP 4
#define TOK_PER_BLOCK (WARPS_PER_BLOCK * TOK_PER_WARP)   // 64
#define NBLOCK (NTOK / TOK_PER_BLOCK)                    // 8192
#define PT_PITCH 130                       // padded pitch for transposed P (conflict-free f32x2 reads)

// smem layout (floats): Pt[128][130] | Pr[128][128] | bc[16 warps][128][4]
#define SMEM_PT_FLOATS (128 * PT_PITCH)                  // 16640
#define SMEM_PR_FLOATS (128 * 128)                       // 16384
#define SMEM_BC_OFF    (SMEM_PT_FLOATS + SMEM_PR_FLOATS) // 33024
#define SMEM_FLOATS    (SMEM_BC_OFF + WARPS_PER_BLOCK * 128 * 4)  // 41216
#define SMEM_BYTES     (SMEM_FLOATS * 4)                 // 164864

typedef unsigned long long u64;

// ---- packed f32x2 helpers (sm_100+/sm_103a); carrier type is u64 for "l" constraint ----
__device__ __forceinline__ u64 f32x2_fma(u64 a, u64 b, u64 c) {
    u64 r;
    asm("fma.rn.f32x2 %0, %1, %2, %3;" : "=l"(r) : "l"(a), "l"(b), "l"(c));
    return r;
}
__device__ __forceinline__ u64 f32x2_dup(float v) {
    u64 r;
    unsigned u = __float_as_uint(v);
    asm("mov.b64 %0, {%1, %2};" : "=l"(r) : "r"(u), "r"(u));
    return r;
}
__device__ __forceinline__ void f32x2_unpack(u64 a, float& lo, float& hi) {
    unsigned x, y;
    asm("mov.b64 {%0, %1}, %2;" : "=r"(x), "=r"(y) : "l"(a));
    lo = __uint_as_float(x);
    hi = __uint_as_float(y);
}

__device__ __forceinline__ float sign_of(float p) {
    return (p > 0.0f) ? 1.0f : ((p < 0.0f) ? -1.0f : 0.0f);
}

__global__ void __launch_bounds__(512, 1)
turboquant_kernel(const float* __restrict__ x,
                  const float* __restrict__ cb,
                  const float* __restrict__ proj,
                  float* __restrict__ o_xhat,
                  float* __restrict__ o_idx,
                  float* __restrict__ o_sign,
                  float* __restrict__ o_norm)
{
    extern __shared__ float smem[];
    float* Pt = smem;                    // [128][PT_PITCH], Pt[d][e] = proj[e][d]
    float* Pr = smem + SMEM_PT_FLOATS;   // [128][128], row-major copy of proj
    const int tid  = threadIdx.x;
    const int lane = tid & 31;
    const int warp = tid >> 5;
    float* bc = smem + SMEM_BC_OFF + warp * (128 * 4);   // per-warp [128][4] broadcast buffer

    // ---- stage P into smem (straight copy + padded transpose) ----
    #pragma unroll
    for (int it = 0; it < 8; ++it) {
        int i  = tid + it * 512;           // float4 index, 0..4095
        int e  = i >> 5;
        int dq = i & 31;
        float4 v = ((const float4*)proj)[i];
        ((float4*)Pr)[i] = v;
        int d0 = 4 * dq;
        Pt[(d0 + 0) * PT_PITCH + e] = v.x;
        Pt[(d0 + 1) * PT_PITCH + e] = v.y;
        Pt[(d0 + 2) * PT_PITCH + e] = v.z;
        Pt[(d0 + 3) * PT_PITCH + e] = v.w;
    }

    const float c0 = cb[0], c1 = cb[1], c2 = cb[2], c3 = cb[3];
    const float b0 = 0.5f * (c0 + c1);
    const float b1 = 0.5f * (c1 + c2);
    const float b2 = 0.5f * (c2 + c3);
    const float scale = 1.2533141373155003f / 128.0f;   // fp32(sqrt(pi/2)) / dim

    __syncthreads();

    const int tok0 = blockIdx.x * TOK_PER_BLOCK + warp * TOK_PER_WARP;

    // ---- Phase A: quantize, residual, norm; residual -> bc[d][t] ----
    float4 mseK[TOK_PER_WARP];
    float  normv[TOK_PER_WARP];
    #pragma unroll
    for (int t = 0; t < TOK_PER_WARP; ++t) {
        const size_t row = (size_t)(tok0 + t) * DIMV;
        float2 xa = *(const float2*)(x + row + 2 * lane);
        float2 xb = *(const float2*)(x + row + 64 + 2 * lane);
        float xs0 = xa.x, xs1 = xa.y, xs2 = xb.x, xs3 = xb.y;

        float rr[4], ii[4], mm[4];
        float ssq = 0.0f;
        {
            float v = xs0; int ix = (v > b0) + (v > b1) + (v > b2);
            float m = (ix == 0) ? c0 : (ix == 1) ? c1 : (ix == 2) ? c2 : c3;
            ii[0] = (float)ix; mm[0] = m; rr[0] = v - m; ssq += rr[0] * rr[0];
        }
        {
            float v = xs1; int ix = (v > b0) + (v > b1) + (v > b2);
            float m = (ix == 0) ? c0 : (ix == 1) ? c1 : (ix == 2) ? c2 : c3;
            ii[1] = (float)ix; mm[1] = m; rr[1] = v - m; ssq += rr[1] * rr[1];
        }
        {
            float v = xs2; int ix = (v > b0) + (v > b1) + (v > b2);
            float m = (ix == 0) ? c0 : (ix == 1) ? c1 : (ix == 2) ? c2 : c3;
            ii[2] = (float)ix; mm[2] = m; rr[2] = v - m; ssq += rr[2] * rr[2];
        }
        {
            float v = xs3; int ix = (v > b0) + (v > b1) + (v > b2);
            float m = (ix == 0) ? c0 : (ix == 1) ? c1 : (ix == 2) ? c2 : c3;
            ii[3] = (float)ix; mm[3] = m; rr[3] = v - m; ssq += rr[3] * rr[3];
        }
        mseK[t] = make_float4(mm[0], mm[1], mm[2], mm[3]);

        bc[(2 * lane + 0) * 4 + t] = rr[0];
        bc[(2 * lane + 1) * 4 + t] = rr[1];
        bc[(64 + 2 * lane + 0) * 4 + t] = rr[2];
        bc[(64 + 2 * lane + 1) * 4 + t] = rr[3];

        if (o_idx) {
            *(float2*)(o_idx + row + 2 * lane)      = make_float2(ii[0], ii[1]);
            *(float2*)(o_idx + row + 64 + 2 * lane) = make_float2(ii[2], ii[3]);
        }

        #pragma unroll
        for (int o = 16; o > 0; o >>= 1) ssq += __shfl_xor_sync(0xffffffffu, ssq, o);
        normv[t] = sqrtf(ssq);
        if (o_norm && lane == t) o_norm[tok0 + t] = normv[t];
    }
    __syncwarp();

    // ---- GEMM1: proj_r[t][e] = sum_d r[t][d] * P[e][d]  (lane owns e = 2l,2l+1,64+2l,65+2l) ----
    u64 a00 = 0, a01 = 0, a10 = 0, a11 = 0, a20 = 0, a21 = 0, a30 = 0, a31 = 0;
    {
        const float* ptp = Pt + 2 * lane;
        #pragma unroll 8
        for (int d = 0; d < DIMV; ++d) {
            float4 rv = *(const float4*)(bc + 4 * d);              // broadcast r of 4 tokens
            u64 p0 = *(const u64*)(ptp + d * PT_PITCH);            // P[e][d], e = 2l,2l+1
            u64 p1 = *(const u64*)(ptp + d * PT_PITCH + 64);       // e = 64+2l, 65+2l
            u64 q;
            q = f32x2_dup(rv.x); a00 = f32x2_fma(p0, q, a00); a01 = f32x2_fma(p1, q, a01);
            q = f32x2_dup(rv.y); a10 = f32x2_fma(p0, q, a10); a11 = f32x2_fma(p1, q, a11);
            q = f32x2_dup(rv.z); a20 = f32x2_fma(p0, q, a20); a21 = f32x2_fma(p1, q, a21);
            q = f32x2_dup(rv.w); a30 = f32x2_fma(p0, q, a30); a31 = f32x2_fma(p1, q, a31);
        }
    }
    __syncwarp();

    // ---- signs: write to gmem + bc[e][t] for GEMM2 ----
    {
        float p0, p1, p2, p3;
        #define DO_SIGN(T, A0, A1)                                                          \
        {                                                                                   \
            f32x2_unpack(A0, p0, p1); f32x2_unpack(A1, p2, p3);                             \
            float s0 = sign_of(p0), s1 = sign_of(p1), s2 = sign_of(p2), s3 = sign_of(p3);   \
            bc[(2 * lane + 0) * 4 + (T)] = s0;                                              \
            bc[(2 * lane + 1) * 4 + (T)] = s1;                                              \
            bc[(64 + 2 * lane + 0) * 4 + (T)] = s2;                                         \
            bc[(64 + 2 * lane + 1) * 4 + (T)] = s3;                                         \
            if (o_sign) {                                                                   \
                const size_t row = (size_t)(tok0 + (T)) * DIMV;                             \
                *(float2*)(o_sign + row + 2 * lane)      = make_float2(s0, s1);             \
                *(float2*)(o_sign + row + 64 + 2 * lane) = make_float2(s2, s3);             \
            }                                                                               \
        }
        DO_SIGN(0, a00, a01)
        DO_SIGN(1, a10, a11)
        DO_SIGN(2, a20, a21)
        DO_SIGN(3, a30, a31)
        #undef DO_SIGN
    }
    __syncwarp();

    // ---- GEMM2: g[t][d] = sum_e s[t][e] * P[e][d]  (lane owns d = 2l,2l+1,64+2l,65+2l) ----
    u64 g00 = 0, g01 = 0, g10 = 0, g11 = 0, g20 = 0, g21 = 0, g30 = 0, g31 = 0;
    {
        const float* prp = Pr + 2 * lane;
        #pragma unroll 8
        for (int e = 0; e < DIMV; ++e) {
            float4 sv = *(const float4*)(bc + 4 * e);              // broadcast signs of 4 tokens
            u64 q0 = *(const u64*)(prp + e * DIMV);                // P[e][d], d = 2l,2l+1
            u64 q1 = *(const u64*)(prp + e * DIMV + 64);           // d = 64+2l, 65+2l
            u64 q;
            q = f32x2_dup(sv.x); g00 = f32x2_fma(q0, q, g00); g01 = f32x2_fma(q1, q, g01);
            q = f32x2_dup(sv.y); g10 = f32x2_fma(q0, q, g10); g11 = f32x2_fma(q1, q, g11);
            q = f32x2_dup(sv.z); g20 = f32x2_fma(q0, q, g20); g21 = f32x2_fma(q1, q, g21);
            q = f32x2_dup(sv.w); g30 = f32x2_fma(q0, q, g30); g31 = f32x2_fma(q1, q, g31);
        }
    }

    // ---- epilogue: x_hat = x_mse + scale * ||r|| * g ----
    {
        float v0, v1, v2, v3;
        #define DO_OUT(T, G0, G1)                                                           \
        {                                                                                   \
            f32x2_unpack(G0, v0, v1); f32x2_unpack(G1, v2, v3);                             \
            const float cf = scale * normv[T];                                              \
            const float4 m = mseK[T];                                                       \
            const size_t row = (size_t)(tok0 + (T)) * DIMV;                                 \
            *(float2*)(o_xhat + row + 2 * lane)      = make_float2(m.x + cf * v0, m.y + cf * v1); \
            *(float2*)(o_xhat + row + 64 + 2 * lane) = make_float2(m.z + cf * v2, m.w + cf * v3); \
        }
        DO_OUT(0, g00, g01)
        DO_OUT(1, g10, g11)
        DO_OUT(2, g20, g21)
        DO_OUT(3, g30, g31)
        #undef DO_OUT
    }
}

extern "C" void kernel_launch(void* const* d_in, const int* in_sizes, int n_in,
                              void* d_out, int out_size)
{
    const float* x    = (const float*)d_in[0];
    const float* cb   = (const float*)d_in[1];
    const float* proj = (const float*)d_in[2];

    float* o_x = (float*)d_out;
    float* o_i = nullptr;
    float* o_s = nullptr;
    float* o_n = nullptr;
    // Expected packing: concat(x_hat, mse_indices, qjl_signs, residual_norm) as f32.
    long long need = 3LL * NELEM_LL + (long long)NTOK;   // 201850880
    if ((long long)out_size >= need) {
        o_i = o_x + NELEM_LL;
        o_s = o_x + 2 * NELEM_LL;
        o_n = o_x + 3 * NELEM_LL;
    }

    cudaFuncSetAttribute(turboquant_kernel,
                         cudaFuncAttributeMaxDynamicSharedMemorySize, SMEM_BYTES);
    turboquant_kernel<<<NBLOCK, 512, SMEM_BYTES>>>(x, cb, proj, o_x, o_i, o_s, o_n);
}

// round 3
// speedup vs baseline: 1.1835x; 1.1835x over previous
#include <cuda_runtime.h>
#include <math.h>

// x[2,32,8192,128] f32, codebook[4] f32, projection[128,128] f32
#define DIMV 128
#define NTOK (2*32*8192)                  // 524288 tokens
#define NELEM_LL (524288LL * 128LL)       // 67108864
#define WARPS_PER_BLOCK 16
#define TOK_PER_WARP 8
#define TOK_PER_BLOCK (WARPS_PER_BLOCK * TOK_PER_WARP)   // 128
#define NBLOCK (NTOK / TOK_PER_BLOCK)                    // 4096
#define PT_PITCH 130

// smem (floats): Pt[128][130] | Prp[128][128] (permuted rows) | bc[16][128][8]
#define SMEM_PT_FLOATS (128 * PT_PITCH)                  // 16640
#define SMEM_PR_FLOATS (128 * 128)                       // 16384
#define SMEM_BC_OFF    (SMEM_PT_FLOATS + SMEM_PR_FLOATS) // 33024
#define SMEM_FLOATS    (SMEM_BC_OFF + WARPS_PER_BLOCK * 128 * 8)  // 49408
#define SMEM_BYTES     (SMEM_FLOATS * 4)                 // 197632

typedef unsigned long long u64;

__device__ __forceinline__ u64 f32x2_fma(u64 a, u64 b, u64 c) {
    u64 r;
    asm("fma.rn.f32x2 %0, %1, %2, %3;" : "=l"(r) : "l"(a), "l"(b), "l"(c));
    return r;
}
__device__ __forceinline__ u64 f32x2_dup(float v) {
    u64 r;
    unsigned u = __float_as_uint(v);
    asm("mov.b64 %0, {%1, %2};" : "=l"(r) : "r"(u), "r"(u));
    return r;
}
__device__ __forceinline__ void f32x2_unpack(u64 a, float& lo, float& hi) {
    unsigned x, y;
    asm("mov.b64 {%0, %1}, %2;" : "=r"(x), "=r"(y) : "l"(a));
    lo = __uint_as_float(x);
    hi = __uint_as_float(y);
}
__device__ __forceinline__ float sign_of(float p) {
    return (p > 0.0f) ? 1.0f : ((p < 0.0f) ? -1.0f : 0.0f);
}

__global__ void __launch_bounds__(512, 1)
turboquant_kernel(const float* __restrict__ x,
                  const float* __restrict__ cb,
                  const float* __restrict__ proj,
                  float* __restrict__ o_xhat,
                  float* __restrict__ o_idx,
                  float* __restrict__ o_sign,
                  float* __restrict__ o_norm)
{
    extern __shared__ float smem[];
    float* Pt  = smem;                    // Pt[d][e] = proj[e][d], pitch 130
    float* Prp = smem + SMEM_PT_FLOATS;   // Prp[rho][d] = proj[e(rho)][d]
    const int tid  = threadIdx.x;
    const int lane = tid & 31;
    const int warp = tid >> 5;
    float* bc = smem + SMEM_BC_OFF + warp * (128 * 8);   // per-warp [128 rows][8 tokens]

    // ---- stage P: transposed copy (Pt) + row-permuted copy (Prp) ----
    // permutation: rho(e) = ((e&1)<<5) | ((e>>6)<<6) | ((e>>1)&31)
    //   so GEMM1-owned e = {2l, 2l+1, 64+2l, 65+2l}  <->  rows {l, 32+l, 64+l, 96+l}
    #pragma unroll
    for (int it = 0; it < 8; ++it) {
        int i  = tid + it * 512;           // float4 index 0..4095
        int e  = i >> 5;
        int dq = i & 31;
        float4 v = ((const float4*)proj)[i];
        int rho = ((e & 1) << 5) | ((e >> 6) << 6) | ((e >> 1) & 31);
        ((float4*)(Prp + rho * DIMV))[dq] = v;
        int d0 = 4 * dq;
        Pt[(d0 + 0) * PT_PITCH + e] = v.x;
        Pt[(d0 + 1) * PT_PITCH + e] = v.y;
        Pt[(d0 + 2) * PT_PITCH + e] = v.z;
        Pt[(d0 + 3) * PT_PITCH + e] = v.w;
    }

    const float c0 = cb[0], c1 = cb[1], c2 = cb[2], c3 = cb[3];
    const float b0 = 0.5f * (c0 + c1);
    const float b1 = 0.5f * (c1 + c2);
    const float b2 = 0.5f * (c2 + c3);
    const float scale = 1.2533141373155003f / 128.0f;

    __syncthreads();

    const int tok0 = blockIdx.x * TOK_PER_BLOCK + warp * TOK_PER_WARP;
    float normv[TOK_PER_WARP];

    // ---- Phase A: quantize, residual -> bc[d][t] (stride-32 element ownership) ----
    #pragma unroll
    for (int t = 0; t < TOK_PER_WARP; ++t) {
        const size_t row = (size_t)(tok0 + t) * DIMV;
        float xv[4];
        xv[0] = x[row + lane];
        xv[1] = x[row + 32 + lane];
        xv[2] = x[row + 64 + lane];
        xv[3] = x[row + 96 + lane];

        float ssq = 0.0f;
        #pragma unroll
        for (int j = 0; j < 4; ++j) {
            float v = xv[j];
            int ix = (v > b0) + (v > b1) + (v > b2);
            float m = (ix == 0) ? c0 : (ix == 1) ? c1 : (ix == 2) ? c2 : c3;
            float r = v - m;
            ssq += r * r;
            bc[(32 * j + lane) * 8 + t] = r;
            if (o_idx) o_idx[row + 32 * j + lane] = (float)ix;
        }

        #pragma unroll
        for (int o = 16; o > 0; o >>= 1) ssq += __shfl_xor_sync(0xffffffffu, ssq, o);
        normv[t] = sqrtf(ssq);
        if (o_norm && lane == t) o_norm[tok0 + t] = normv[t];
    }
    __syncwarp();

    // ---- GEMM1: proj_r[t][e] = sum_d r[t][d]*P[e][d]; lane owns e={2l,2l+1,64+2l,65+2l} ----
    u64 acc[16];
    #pragma unroll
    for (int i = 0; i < 16; ++i) acc[i] = 0;
    {
        const float* ptp = Pt + 2 * lane;
        #pragma unroll 8
        for (int d = 0; d < DIMV; ++d) {
            float4 rA = *(const float4*)(bc + 8 * d);       // tokens 0..3
            float4 rB = *(const float4*)(bc + 8 * d + 4);   // tokens 4..7
            u64 p0 = *(const u64*)(ptp + d * PT_PITCH);
            u64 p1 = *(const u64*)(ptp + d * PT_PITCH + 64);
            u64 q;
            q = f32x2_dup(rA.x); acc[0]  = f32x2_fma(p0, q, acc[0]);  acc[1]  = f32x2_fma(p1, q, acc[1]);
            q = f32x2_dup(rA.y); acc[2]  = f32x2_fma(p0, q, acc[2]);  acc[3]  = f32x2_fma(p1, q, acc[3]);
            q = f32x2_dup(rA.z); acc[4]  = f32x2_fma(p0, q, acc[4]);  acc[5]  = f32x2_fma(p1, q, acc[5]);
            q = f32x2_dup(rA.w); acc[6]  = f32x2_fma(p0, q, acc[6]);  acc[7]  = f32x2_fma(p1, q, acc[7]);
            q = f32x2_dup(rB.x); acc[8]  = f32x2_fma(p0, q, acc[8]);  acc[9]  = f32x2_fma(p1, q, acc[9]);
            q = f32x2_dup(rB.y); acc[10] = f32x2_fma(p0, q, acc[10]); acc[11] = f32x2_fma(p1, q, acc[11]);
            q = f32x2_dup(rB.z); acc[12] = f32x2_fma(p0, q, acc[12]); acc[13] = f32x2_fma(p1, q, acc[13]);
            q = f32x2_dup(rB.w); acc[14] = f32x2_fma(p0, q, acc[14]); acc[15] = f32x2_fma(p1, q, acc[15]);
        }
    }
    __syncwarp();

    // ---- signs -> bc rows {l,32+l,64+l,96+l} (matching Prp permutation) + gmem ----
    #pragma unroll
    for (int t = 0; t < TOK_PER_WARP; ++t) {
        float p0, p1, p2, p3;
        f32x2_unpack(acc[2 * t],     p0, p1);   // e = 2l, 2l+1
        f32x2_unpack(acc[2 * t + 1], p2, p3);   // e = 64+2l, 65+2l
        float s0 = sign_of(p0), s1 = sign_of(p1), s2 = sign_of(p2), s3 = sign_of(p3);
        bc[(lane) * 8 + t]      = s0;
        bc[(32 + lane) * 8 + t] = s1;
        bc[(64 + lane) * 8 + t] = s2;
        bc[(96 + lane) * 8 + t] = s3;
        if (o_sign) {
            const size_t row = (size_t)(tok0 + t) * DIMV;
            *(float2*)(o_sign + row + 2 * lane)      = make_float2(s0, s1);
            *(float2*)(o_sign + row + 64 + 2 * lane) = make_float2(s2, s3);
        }
    }
    __syncwarp();

    // ---- GEMM2: g[t][d] = sum_e s[t][e]*P[e][d]; lane owns d={2l,2l+1,64+2l,65+2l} ----
    u64 gcc[16];
    #pragma unroll
    for (int i = 0; i < 16; ++i) gcc[i] = 0;
    {
        const float* prp = Prp + 2 * lane;
        #pragma unroll 8
        for (int e = 0; e < DIMV; ++e) {      // iterates rho; Prp row matches bc row
            float4 sA = *(const float4*)(bc + 8 * e);
            float4 sB = *(const float4*)(bc + 8 * e + 4);
            u64 q0 = *(const u64*)(prp + e * DIMV);
            u64 q1 = *(const u64*)(prp + e * DIMV + 64);
            u64 q;
            q = f32x2_dup(sA.x); gcc[0]  = f32x2_fma(q0, q, gcc[0]);  gcc[1]  = f32x2_fma(q1, q, gcc[1]);
            q = f32x2_dup(sA.y); gcc[2]  = f32x2_fma(q0, q, gcc[2]);  gcc[3]  = f32x2_fma(q1, q, gcc[3]);
            q = f32x2_dup(sA.z); gcc[4]  = f32x2_fma(q0, q, gcc[4]);  gcc[5]  = f32x2_fma(q1, q, gcc[5]);
            q = f32x2_dup(sA.w); gcc[6]  = f32x2_fma(q0, q, gcc[6]);  gcc[7]  = f32x2_fma(q1, q, gcc[7]);
            q = f32x2_dup(sB.x); gcc[8]  = f32x2_fma(q0, q, gcc[8]);  gcc[9]  = f32x2_fma(q1, q, gcc[9]);
            q = f32x2_dup(sB.y); gcc[10] = f32x2_fma(q0, q, gcc[10]); gcc[11] = f32x2_fma(q1, q, gcc[11]);
            q = f32x2_dup(sB.z); gcc[12] = f32x2_fma(q0, q, gcc[12]); gcc[13] = f32x2_fma(q1, q, gcc[13]);
            q = f32x2_dup(sB.w); gcc[14] = f32x2_fma(q0, q, gcc[14]); gcc[15] = f32x2_fma(q1, q, gcc[15]);
        }
    }

    // ---- epilogue: reload x, recompute mse value, x_hat = m + scale*||r||*g ----
    #pragma unroll
    for (int t = 0; t < TOK_PER_WARP; ++t) {
        const size_t row = (size_t)(tok0 + t) * DIMV;
        float2 xa = *(const float2*)(x + row + 2 * lane);
        float2 xb = *(const float2*)(x + row + 64 + 2 * lane);
        float v0, v1, v2, v3;
        f32x2_unpack(gcc[2 * t],     v0, v1);
        f32x2_unpack(gcc[2 * t + 1], v2, v3);
        const float cf = scale * normv[t];
        float m;
        int ix;
        float4 xm;
        ix = (xa.x > b0) + (xa.x > b1) + (xa.x > b2);
        m  = (ix == 0) ? c0 : (ix == 1) ? c1 : (ix == 2) ? c2 : c3;  xm.x = m;
        ix = (xa.y > b0) + (xa.y > b1) + (xa.y > b2);
        m  = (ix == 0) ? c0 : (ix == 1) ? c1 : (ix == 2) ? c2 : c3;  xm.y = m;
        ix = (xb.x > b0) + (xb.x > b1) + (xb.x > b2);
        m  = (ix == 0) ? c0 : (ix == 1) ? c1 : (ix == 2) ? c2 : c3;  xm.z = m;
        ix = (xb.y > b0) + (xb.y > b1) + (xb.y > b2);
        m  = (ix == 0) ? c0 : (ix == 1) ? c1 : (ix == 2) ? c2 : c3;  xm.w = m;
        *(float2*)(o_xhat + row + 2 * lane)      = make_float2(xm.x + cf * v0, xm.y + cf * v1);
        *(float2*)(o_xhat + row + 64 + 2 * lane) = make_float2(xm.z + cf * v2, xm.w + cf * v3);
    }
}

extern "C" void kernel_launch(void* const* d_in, const int* in_sizes, int n_in,
                              void* d_out, int out_size)
{
    const float* x    = (const float*)d_in[0];
    const float* cb   = (const float*)d_in[1];
    const float* proj = (const float*)d_in[2];

    float* o_x = (float*)d_out;
    float* o_i = nullptr;
    float* o_s = nullptr;
    float* o_n = nullptr;
    long long need = 3LL * NELEM_LL + (long long)NTOK;   // 201850880
    if ((long long)out_size >= need) {
        o_i = o_x + NELEM_LL;
        o_s = o_x + 2 * NELEM_LL;
        o_n = o_x + 3 * NELEM_LL;
    }

    cudaFuncSetAttribute(turboquant_kernel,
                         cudaFuncAttributeMaxDynamicSharedMemorySize, SMEM_BYTES);
    turboquant_kernel<<<NBLOCK, 512, SMEM_BYTES>>>(x, cb, proj, o_x, o_i, o_s, o_n);
}

// round 5
// speedup vs baseline: 1.5026x; 1.2697x over previous
#include <cuda_runtime.h>
#include <cuda_fp16.h>
#include <stdint.h>

#define DIMV 128
#define NTOK (2*32*8192)
#define NELEM_LL (524288LL * 128LL)
#define NTHREADS 256
#define NBLOCK (NTOK / 128)          // 4096 CTAs, 128 tokens each
#define PITCH 136                    // fp16 elements per tile row (272B)

// smem byte offsets
#define SM_R1   0                    // r1 tile [128][136] fp16 (34816B)
#define SM_R2   34816                // r2 tile; later: sign tile
#define SM_PB   69632                // streamed P tile buffer
#define SM_IDX  104448               // packed 2-bit indices, 128*32 B
#define SM_NORM 108544               // 128 f32
#define SM_TOTAL 109056

// P splits in device scratch (pitch 136)
__device__ __align__(16) __half gP1[128 * PITCH];
__device__ __align__(16) __half gP2[128 * PITCH];
__device__ __align__(16) __half gPT1[128 * PITCH];
__device__ __align__(16) __half gPT2[128 * PITCH];

__device__ __forceinline__ uint32_t hpack(__half a, __half b){
    __half2 t = __halves2half2(a, b);
    return *reinterpret_cast<uint32_t*>(&t);
}
__device__ __forceinline__ float sign_of(float p){
    return (p > 0.0f) ? 1.0f : ((p < 0.0f) ? -1.0f : 0.0f);
}

__global__ void prep_kernel(const float* __restrict__ proj){
    int i = blockIdx.x * blockDim.x + threadIdx.x;   // 0..16383
    int e = i >> 7, d = i & 127;
    float v = proj[i];
    __half h1 = __float2half_rn(v);
    __half h2 = __float2half_rn(v - __half2float(h1));
    gP1[e * PITCH + d] = h1;
    gP2[e * PITCH + d] = h2;
    gPT1[d * PITCH + e] = h1;
    gPT2[d * PITCH + e] = h2;
}

extern __shared__ char smc[];

__device__ __forceinline__ void copyP(const __half* src){
    const uint4* s = (const uint4*)src;
    uint4* dst = (uint4*)(smc + SM_PB);
    #pragma unroll
    for (int i = threadIdx.x; i < (128 * PITCH * 2) / 16; i += NTHREADS)
        dst[i] = s[i];
}

// one GEMM product: acc[2][8][4] += A(32x128 from Ab) * B^T-ish (Bb), m16n8k16 fp16
__device__ __forceinline__ void mma_prod(float acc[2][8][4], const char* Ab, const char* Bb,
                                         int mrow, int ncol, int g, int tig){
    #pragma unroll
    for (int kt = 0; kt < 8; kt++){
        uint32_t a[2][4];
        #pragma unroll
        for (int mt = 0; mt < 2; mt++){
            const char* ap = Ab + ((mrow + 16 * mt + g) * PITCH + kt * 16 + 2 * tig) * 2;
            a[mt][0] = *(const uint32_t*)(ap);
            a[mt][1] = *(const uint32_t*)(ap + 8 * PITCH * 2);
            a[mt][2] = *(const uint32_t*)(ap + 16);
            a[mt][3] = *(const uint32_t*)(ap + 8 * PITCH * 2 + 16);
        }
        #pragma unroll
        for (int nt = 0; nt < 8; nt++){
            const char* bp = Bb + ((ncol + 8 * nt + g) * PITCH + kt * 16 + 2 * tig) * 2;
            uint32_t b0 = *(const uint32_t*)(bp);
            uint32_t b1 = *(const uint32_t*)(bp + 16);
            #pragma unroll
            for (int mt = 0; mt < 2; mt++)
                asm volatile("mma.sync.aligned.m16n8k16.row.col.f32.f16.f16.f32 "
                    "{%0,%1,%2,%3}, {%4,%5,%6,%7}, {%8,%9}, {%0,%1,%2,%3};"
                    : "+f"(acc[mt][nt][0]), "+f"(acc[mt][nt][1]),
                      "+f"(acc[mt][nt][2]), "+f"(acc[mt][nt][3])
                    : "r"(a[mt][0]), "r"(a[mt][1]), "r"(a[mt][2]), "r"(a[mt][3]),
                      "r"(b0), "r"(b1));
        }
    }
}

__global__ void __launch_bounds__(NTHREADS)
turboquant_mma_kernel(const float* __restrict__ x,
                      const float* __restrict__ cb,
                      float* __restrict__ o_xhat,
                      float* __restrict__ o_idx,
                      float* __restrict__ o_sign,
                      float* __restrict__ o_norm)
{
    const int tid  = threadIdx.x;
    const int lane = tid & 31;
    const int warp = tid >> 5;
    const int g    = lane >> 2;
    const int tig  = lane & 3;
    const int mrow = (warp >> 1) * 32;
    const int ncol = (warp & 1) * 64;
    const int tok0 = blockIdx.x * 128;

    float* norms = (float*)(smc + SM_NORM);
    unsigned char* idxb = (unsigned char*)(smc + SM_IDX);

    const float c0 = cb[0], c1 = cb[1], c2 = cb[2], c3 = cb[3];
    const float b0 = 0.5f * (c0 + c1), b1 = 0.5f * (c1 + c2), b2 = 0.5f * (c2 + c3);
    const float scale = 1.2533141373155003f / 128.0f;

    // ---- copy P1 + phase A (independent writes) ----
    copyP(gP1);
    {
        const int tok = tid >> 1, hf = tid & 1;
        const float* xr = x + (size_t)(tok0 + tok) * DIMV + hf * 64;
        char* r1t = smc + SM_R1 + (tok * PITCH + hf * 64) * 2;
        char* r2t = smc + SM_R2 + (tok * PITCH + hf * 64) * 2;
        float ssq = 0.0f;
        uint32_t packed[4] = {0, 0, 0, 0};
        #pragma unroll
        for (int j = 0; j < 16; j++){
            float4 xv = ((const float4*)xr)[j];
            float vf[4] = {xv.x, xv.y, xv.z, xv.w};
            __half h1[4], h2[4];
            float iv[4];
            #pragma unroll
            for (int q = 0; q < 4; q++){
                float v = vf[q];
                int ix = (v > b0) + (v > b1) + (v > b2);
                float m = (ix == 0) ? c0 : (ix == 1) ? c1 : (ix == 2) ? c2 : c3;
                float r = v - m;
                ssq += r * r;
                iv[q] = (float)ix;
                packed[j >> 2] |= ((uint32_t)ix) << (((j & 3) * 4 + q) * 2);
                h1[q] = __float2half_rn(r);
                h2[q] = __float2half_rn(r - __half2float(h1[q]));
            }
            uint2 w1, w2;
            w1.x = hpack(h1[0], h1[1]); w1.y = hpack(h1[2], h1[3]);
            w2.x = hpack(h2[0], h2[1]); w2.y = hpack(h2[2], h2[3]);
            *(uint2*)(r1t + j * 8) = w1;
            *(uint2*)(r2t + j * 8) = w2;
            if (o_idx)
                *(float4*)(o_idx + (size_t)(tok0 + tok) * DIMV + hf * 64 + 4 * j) =
                    make_float4(iv[0], iv[1], iv[2], iv[3]);
        }
        ssq += __shfl_xor_sync(0xffffffffu, ssq, 1);
        if (hf == 0){
            float nv = sqrtf(ssq);
            norms[tok] = nv;
            if (o_norm) o_norm[tok0 + tok] = nv;
        }
        *(uint4*)(idxb + tok * 32 + hf * 16) = make_uint4(packed[0], packed[1], packed[2], packed[3]);
    }
    __syncthreads();

    // ---- GEMM1 ----
    float acc1[2][8][4];
    #pragma unroll
    for (int i = 0; i < 2; i++)
        #pragma unroll
        for (int j = 0; j < 8; j++)
            #pragma unroll
            for (int k = 0; k < 4; k++) acc1[i][j][k] = 0.0f;

    mma_prod(acc1, smc + SM_R1, smc + SM_PB, mrow, ncol, g, tig);
    mma_prod(acc1, smc + SM_R2, smc + SM_PB, mrow, ncol, g, tig);
    __syncthreads();
    copyP(gP2);
    __syncthreads();
    mma_prod(acc1, smc + SM_R1, smc + SM_PB, mrow, ncol, g, tig);
    mma_prod(acc1, smc + SM_R2, smc + SM_PB, mrow, ncol, g, tig);
    __syncthreads();   // everyone done reading R2 and PB

    // ---- signs (in-register) -> o_sign + sign tile (R2 slot); also stream PT2 ----
    {
        const __half hp1 = __float2half_rn(1.0f), hm1 = __float2half_rn(-1.0f), hz = __float2half_rn(0.0f);
        #pragma unroll
        for (int mt = 0; mt < 2; mt++){
            const int r0 = mrow + 16 * mt + g;
            #pragma unroll
            for (int nt = 0; nt < 8; nt++){
                const int cc = ncol + 8 * nt + 2 * tig;
                float s00 = sign_of(acc1[mt][nt][0]);
                float s01 = sign_of(acc1[mt][nt][1]);
                float s10 = sign_of(acc1[mt][nt][2]);
                float s11 = sign_of(acc1[mt][nt][3]);
                if (o_sign){
                    *(float2*)(o_sign + (size_t)(tok0 + r0) * DIMV + cc)     = make_float2(s00, s01);
                    *(float2*)(o_sign + (size_t)(tok0 + r0 + 8) * DIMV + cc) = make_float2(s10, s11);
                }
                __half e00 = (s00 > 0.f) ? hp1 : ((s00 < 0.f) ? hm1 : hz);
                __half e01 = (s01 > 0.f) ? hp1 : ((s01 < 0.f) ? hm1 : hz);
                __half e10 = (s10 > 0.f) ? hp1 : ((s10 < 0.f) ? hm1 : hz);
                __half e11 = (s11 > 0.f) ? hp1 : ((s11 < 0.f) ? hm1 : hz);
                *(uint32_t*)(smc + SM_R2 + (r0 * PITCH + cc) * 2)       = hpack(e00, e01);
                *(uint32_t*)(smc + SM_R2 + ((r0 + 8) * PITCH + cc) * 2) = hpack(e10, e11);
            }
        }
    }
    copyP(gPT2);
    __syncthreads();

    // ---- GEMM2 ----
    float acc2[2][8][4];
    #pragma unroll
    for (int i = 0; i < 2; i++)
        #pragma unroll
        for (int j = 0; j < 8; j++)
            #pragma unroll
            for (int k = 0; k < 4; k++) acc2[i][j][k] = 0.0f;

    mma_prod(acc2, smc + SM_R2, smc + SM_PB, mrow, ncol, g, tig);
    __syncthreads();
    copyP(gPT1);
    __syncthreads();
    mma_prod(acc2, smc + SM_R2, smc + SM_PB, mrow, ncol, g, tig);

    // ---- epilogue: x_hat = cb[idx] + scale*||r||*g ----
    #pragma unroll
    for (int mt = 0; mt < 2; mt++){
        const int r0 = mrow + 16 * mt + g;
        const float cf0 = scale * norms[r0];
        const float cf1 = scale * norms[r0 + 8];
        #pragma unroll
        for (int nt = 0; nt < 8; nt++){
            const int cc = ncol + 8 * nt + 2 * tig;
            const int sh = 2 * (cc & 3);
            unsigned bA = idxb[r0 * 32 + (cc >> 2)];
            unsigned bB = idxb[(r0 + 8) * 32 + (cc >> 2)];
            unsigned i00 = (bA >> sh) & 3u, i01 = (bA >> (sh + 2)) & 3u;
            unsigned i10 = (bB >> sh) & 3u, i11 = (bB >> (sh + 2)) & 3u;
            float m00 = (i00 == 0) ? c0 : (i00 == 1) ? c1 : (i00 == 2) ? c2 : c3;
            float m01 = (i01 == 0) ? c0 : (i01 == 1) ? c1 : (i01 == 2) ? c2 : c3;
            float m10 = (i10 == 0) ? c0 : (i10 == 1) ? c1 : (i10 == 2) ? c2 : c3;
            float m11 = (i11 == 0) ? c0 : (i11 == 1) ? c1 : (i11 == 2) ? c2 : c3;
            *(float2*)(o_xhat + (size_t)(tok0 + r0) * DIMV + cc) =
                make_float2(fmaf(cf0, acc2[mt][nt][0], m00), fmaf(cf0, acc2[mt][nt][1], m01));
            *(float2*)(o_xhat + (size_t)(tok0 + r0 + 8) * DIMV + cc) =
                make_float2(fmaf(cf1, acc2[mt][nt][2], m10), fmaf(cf1, acc2[mt][nt][3], m11));
        }
    }
}

extern "C" void kernel_launch(void* const* d_in, const int* in_sizes, int n_in,
                              void* d_out, int out_size)
{
    const float* x    = (const float*)d_in[0];
    const float* cb   = (const float*)d_in[1];
    const float* proj = (const float*)d_in[2];

    float* o_x = (float*)d_out;
    float* o_i = nullptr;
    float* o_s = nullptr;
    float* o_n = nullptr;
    long long need = 3LL * NELEM_LL + (long long)NTOK;
    if ((long long)out_size >= need){
        o_i = o_x + NELEM_LL;
        o_s = o_x + 2 * NELEM_LL;
        o_n = o_x + 3 * NELEM_LL;
    }

    prep_kernel<<<64, 256>>>(proj);
    cudaFuncSetAttribute(turboquant_mma_kernel,
                         cudaFuncAttributeMaxDynamicSharedMemorySize, SM_TOTAL);
    turboquant_mma_kernel<<<NBLOCK, NTHREADS, SM_TOTAL>>>(x, cb, o_x, o_i, o_s, o_n);
}

// round 6
// speedup vs baseline: 1.5926x; 1.0598x over previous
#include <cuda_runtime.h>
#include <cuda_fp16.h>
#include <stdint.h>

#define DIMV 128
#define NTOK (2*32*8192)
#define NELEM_LL (524288LL * 128LL)
#define NTHREADS 256
#define NBLOCK (NTOK / 128)          // 4096 CTAs, 128 tokens each
#define PITCH 136                    // fp16 elems per tile row (272B)
#define ROWB (PITCH * 2)             // 272

// smem byte offsets
#define SM_R1   0
#define SM_R2   34816                // r2 tile; later: sign tile
#define SM_PB   69632                // streamed P tile buffer
#define SM_IDX  104448               // packed 2-bit indices, 128*32 B
#define SM_NORM 108544               // 128 f32
#define SM_TOTAL 109056

__device__ __align__(16) __half gP1[128 * PITCH];
__device__ __align__(16) __half gP2[128 * PITCH];
__device__ __align__(16) __half gPT1[128 * PITCH];
__device__ __align__(16) __half gPT2[128 * PITCH];

__device__ __forceinline__ uint32_t hpack(__half a, __half b){
    __half2 t = __halves2half2(a, b);
    return *reinterpret_cast<uint32_t*>(&t);
}
__device__ __forceinline__ float sign_of(float p){
    return (p > 0.0f) ? 1.0f : ((p < 0.0f) ? -1.0f : 0.0f);
}
__device__ __forceinline__ uint32_t su(const void* p){
    uint32_t a;
    asm("{ .reg .u64 t; cvta.to.shared.u64 t, %1; cvt.u32.u64 %0, t; }" : "=r"(a) : "l"(p));
    return a;
}

__global__ void prep_kernel(const float* __restrict__ proj){
    int i = blockIdx.x * blockDim.x + threadIdx.x;   // 0..16383
    int e = i >> 7, d = i & 127;
    float v = proj[i];
    __half h1 = __float2half_rn(v);
    __half h2 = __float2half_rn(v - __half2float(h1));
    gP1[e * PITCH + d] = h1;
    gP2[e * PITCH + d] = h2;
    gPT1[d * PITCH + e] = h1;
    gPT2[d * PITCH + e] = h2;
}

extern __shared__ char smc[];

__device__ __forceinline__ void copyP(const __half* src){
    const uint4* s = (const uint4*)src;
    uint4* dst = (uint4*)(smc + SM_PB);
    #pragma unroll
    for (int i = threadIdx.x; i < (128 * ROWB) / 16; i += NTHREADS)
        dst[i] = s[i];
}

// one GEMM product via ldmatrix; aB/bB are per-lane ldmatrix base addrs (shared space)
__device__ __forceinline__ void mma_prod(float acc[2][8][4], uint32_t aB, uint32_t bB){
    #pragma unroll
    for (int kt = 0; kt < 8; kt++){
        uint32_t a[2][4];
        #pragma unroll
        for (int mt = 0; mt < 2; mt++)
            asm volatile("ldmatrix.sync.aligned.m8n8.x4.shared.b16 {%0,%1,%2,%3}, [%4];"
                : "=r"(a[mt][0]), "=r"(a[mt][1]), "=r"(a[mt][2]), "=r"(a[mt][3])
                : "r"(aB + mt * (16 * ROWB) + kt * 32));
        uint32_t b[8][2];
        #pragma unroll
        for (int np = 0; np < 4; np++)
            asm volatile("ldmatrix.sync.aligned.m8n8.x4.shared.b16 {%0,%1,%2,%3}, [%4];"
                : "=r"(b[2*np][0]), "=r"(b[2*np][1]), "=r"(b[2*np+1][0]), "=r"(b[2*np+1][1])
                : "r"(bB + np * (16 * ROWB) + kt * 32));
        #pragma unroll
        for (int nt = 0; nt < 8; nt++)
            #pragma unroll
            for (int mt = 0; mt < 2; mt++)
                asm volatile("mma.sync.aligned.m16n8k16.row.col.f32.f16.f16.f32 "
                    "{%0,%1,%2,%3}, {%4,%5,%6,%7}, {%8,%9}, {%0,%1,%2,%3};"
                    : "+f"(acc[mt][nt][0]), "+f"(acc[mt][nt][1]),
                      "+f"(acc[mt][nt][2]), "+f"(acc[mt][nt][3])
                    : "r"(a[mt][0]), "r"(a[mt][1]), "r"(a[mt][2]), "r"(a[mt][3]),
                      "r"(b[nt][0]), "r"(b[nt][1]));
    }
}

__global__ void __launch_bounds__(NTHREADS, 2)
turboquant_mma_kernel(const float* __restrict__ x,
                      const float* __restrict__ cb,
                      float* __restrict__ o_xhat,
                      float* __restrict__ o_idx,
                      float* __restrict__ o_sign,
                      float* __restrict__ o_norm)
{
    const int tid  = threadIdx.x;
    const int lane = tid & 31;
    const int warp = tid >> 5;
    const int g    = lane >> 2;
    const int tig  = lane & 3;
    const int mrow = (warp >> 1) * 32;
    const int ncol = (warp & 1) * 64;
    const int tok0 = blockIdx.x * 128;

    float* norms = (float*)(smc + SM_NORM);
    unsigned char* idxb = (unsigned char*)(smc + SM_IDX);

    const float c0 = cb[0], c1 = cb[1], c2 = cb[2], c3 = cb[3];
    const float b0 = 0.5f * (c0 + c1), b1 = 0.5f * (c1 + c2), b2 = 0.5f * (c2 + c3);
    const float scale = 1.2533141373155003f / 128.0f;

    // per-lane ldmatrix base offsets (within a tile)
    const uint32_t aLane = (uint32_t)((mrow + (lane & 15)) * ROWB + (lane >> 4) * 16);
    const uint32_t bLane = (uint32_t)((ncol + (lane & 7) + 8 * (lane >> 4)) * ROWB + ((lane >> 3) & 1) * 16);
    const uint32_t sR1 = su(smc + SM_R1), sR2 = su(smc + SM_R2), sPB = su(smc + SM_PB);

    // ---- copy P1 + phase A ----
    copyP(gP1);
    {
        const int tok = tid >> 1, hf = tid & 1;
        const float* xr = x + (size_t)(tok0 + tok) * DIMV + hf * 64;
        char* r1t = smc + SM_R1 + (tok * PITCH + hf * 64) * 2;
        char* r2t = smc + SM_R2 + (tok * PITCH + hf * 64) * 2;
        float ssq = 0.0f;
        #pragma unroll
        for (int ob = 0; ob < 4; ob++){
            uint32_t packed = 0;
            #pragma unroll
            for (int ji = 0; ji < 4; ji++){
                const int j = ob * 4 + ji;
                float4 xv = ((const float4*)xr)[j];
                float vf[4] = {xv.x, xv.y, xv.z, xv.w};
                __half h1[4], h2[4];
                float iv[4];
                #pragma unroll
                for (int q = 0; q < 4; q++){
                    float v = vf[q];
                    int ix = (v > b0) + (v > b1) + (v > b2);
                    float m = (ix == 0) ? c0 : (ix == 1) ? c1 : (ix == 2) ? c2 : c3;
                    float r = v - m;
                    ssq += r * r;
                    iv[q] = (float)ix;
                    packed |= ((uint32_t)ix) << ((ji * 4 + q) * 2);
                    h1[q] = __float2half_rn(r);
                    h2[q] = __float2half_rn(r - __half2float(h1[q]));
                }
                uint2 w1, w2;
                w1.x = hpack(h1[0], h1[1]); w1.y = hpack(h1[2], h1[3]);
                w2.x = hpack(h2[0], h2[1]); w2.y = hpack(h2[2], h2[3]);
                *(uint2*)(r1t + j * 8) = w1;
                *(uint2*)(r2t + j * 8) = w2;
                if (o_idx)
                    *(float4*)(o_idx + (size_t)(tok0 + tok) * DIMV + hf * 64 + 4 * j) =
                        make_float4(iv[0], iv[1], iv[2], iv[3]);
            }
            *(uint32_t*)(idxb + tok * 32 + hf * 16 + ob * 4) = packed;
        }
        ssq += __shfl_xor_sync(0xffffffffu, ssq, 1);
        if (hf == 0){
            float nv = sqrtf(ssq);
            norms[tok] = nv;
            if (o_norm) o_norm[tok0 + tok] = nv;
        }
    }
    __syncthreads();

    // ---- GEMM1: (r1+r2)(P1+P2) ----
    float acc1[2][8][4];
    #pragma unroll
    for (int i = 0; i < 2; i++)
        #pragma unroll
        for (int j = 0; j < 8; j++)
            #pragma unroll
            for (int k = 0; k < 4; k++) acc1[i][j][k] = 0.0f;

    mma_prod(acc1, sR1 + aLane, sPB + bLane);
    mma_prod(acc1, sR2 + aLane, sPB + bLane);
    __syncthreads();
    copyP(gP2);
    __syncthreads();
    mma_prod(acc1, sR1 + aLane, sPB + bLane);
    mma_prod(acc1, sR2 + aLane, sPB + bLane);
    __syncthreads();   // done reading R2 + PB

    // ---- signs -> o_sign + sign tile in R2 slot; stream PT2 ----
    {
        const __half hp1 = __float2half_rn(1.0f), hm1 = __float2half_rn(-1.0f), hz = __float2half_rn(0.0f);
        #pragma unroll
        for (int mt = 0; mt < 2; mt++){
            const int r0 = mrow + 16 * mt + g;
            #pragma unroll
            for (int nt = 0; nt < 8; nt++){
                const int cc = ncol + 8 * nt + 2 * tig;
                float s00 = sign_of(acc1[mt][nt][0]);
                float s01 = sign_of(acc1[mt][nt][1]);
                float s10 = sign_of(acc1[mt][nt][2]);
                float s11 = sign_of(acc1[mt][nt][3]);
                if (o_sign){
                    *(float2*)(o_sign + (size_t)(tok0 + r0) * DIMV + cc)     = make_float2(s00, s01);
                    *(float2*)(o_sign + (size_t)(tok0 + r0 + 8) * DIMV + cc) = make_float2(s10, s11);
                }
                __half e00 = (s00 > 0.f) ? hp1 : ((s00 < 0.f) ? hm1 : hz);
                __half e01 = (s01 > 0.f) ? hp1 : ((s01 < 0.f) ? hm1 : hz);
                __half e10 = (s10 > 0.f) ? hp1 : ((s10 < 0.f) ? hm1 : hz);
                __half e11 = (s11 > 0.f) ? hp1 : ((s11 < 0.f) ? hm1 : hz);
                *(uint32_t*)(smc + SM_R2 + (r0 * PITCH + cc) * 2)       = hpack(e00, e01);
                *(uint32_t*)(smc + SM_R2 + ((r0 + 8) * PITCH + cc) * 2) = hpack(e10, e11);
            }
        }
    }
    copyP(gPT2);
    __syncthreads();

    // ---- GEMM2: signs * (PT2 then PT1) ----
    float acc2[2][8][4];
    #pragma unroll
    for (int i = 0; i < 2; i++)
        #pragma unroll
        for (int j = 0; j < 8; j++)
            #pragma unroll
            for (int k = 0; k < 4; k++) acc2[i][j][k] = 0.0f;

    mma_prod(acc2, sR2 + aLane, sPB + bLane);
    __syncthreads();
    copyP(gPT1);
    __syncthreads();
    mma_prod(acc2, sR2 + aLane, sPB + bLane);

    // ---- epilogue ----
    #pragma unroll
    for (int mt = 0; mt < 2; mt++){
        const int r0 = mrow + 16 * mt + g;
        const float cf0 = scale * norms[r0];
        const float cf1 = scale * norms[r0 + 8];
        #pragma unroll
        for (int nt = 0; nt < 8; nt++){
            const int cc = ncol + 8 * nt + 2 * tig;
            const int sh = 2 * (cc & 3);
            unsigned bA = idxb[r0 * 32 + (cc >> 2)];
            unsigned bB = idxb[(r0 + 8) * 32 + (cc >> 2)];
            unsigned i00 = (bA >> sh) & 3u, i01 = (bA >> (sh + 2)) & 3u;
            unsigned i10 = (bB >> sh) & 3u, i11 = (bB >> (sh + 2)) & 3u;
            float m00 = (i00 == 0) ? c0 : (i00 == 1) ? c1 : (i00 == 2) ? c2 : c3;
            float m01 = (i01 == 0) ? c0 : (i01 == 1) ? c1 : (i01 == 2) ? c2 : c3;
            float m10 = (i10 == 0) ? c0 : (i10 == 1) ? c1 : (i10 == 2) ? c2 : c3;
            float m11 = (i11 == 0) ? c0 : (i11 == 1) ? c1 : (i11 == 2) ? c2 : c3;
            *(float2*)(o_xhat + (size_t)(tok0 + r0) * DIMV + cc) =
                make_float2(fmaf(cf0, acc2[mt][nt][0], m00), fmaf(cf0, acc2[mt][nt][1], m01));
            *(float2*)(o_xhat + (size_t)(tok0 + r0 + 8) * DIMV + cc) =
                make_float2(fmaf(cf1, acc2[mt][nt][2], m10), fmaf(cf1, acc2[mt][nt][3], m11));
        }
    }
}

extern "C" void kernel_launch(void* const* d_in, const int* in_sizes, int n_in,
                              void* d_out, int out_size)
{
    const float* x    = (const float*)d_in[0];
    const float* cb   = (const float*)d_in[1];
    const float* proj = (const float*)d_in[2];

    float* o_x = (float*)d_out;
    float* o_i = nullptr;
    float* o_s = nullptr;
    float* o_n = nullptr;
    long long need = 3LL * NELEM_LL + (long long)NTOK;
    if ((long long)out_size >= need){
        o_i = o_x + NELEM_LL;
        o_s = o_x + 2 * NELEM_LL;
        o_n = o_x + 3 * NELEM_LL;
    }

    prep_kernel<<<64, 256>>>(proj);
    cudaFuncSetAttribute(turboquant_mma_kernel,
                         cudaFuncAttributeMaxDynamicSharedMemorySize, SM_TOTAL);
    turboquant_mma_kernel<<<NBLOCK, NTHREADS, SM_TOTAL>>>(x, cb, o_x, o_i, o_s, o_n);
}